// round 12
// baseline (speedup 1.0000x reference)
#include <cuda_runtime.h>
#include <cuda_fp16.h>
#include <cstdint>

typedef unsigned long long ull;

#define QSCALE 0.17677669529663687f

// fp16 B-fragment images, n ordering: [0,256)=Wq, [256,512)=Wkv.k, [512,768)=Wkv.v, [768,1024)=Wp
__device__ uint32_t g_wH[128][16][32][2];

// ---------------- helpers ----------------
__device__ __forceinline__ uint32_t hpack(float a, float b) {
    __half2 h = __floats2half2_rn(a, b);
    return *(uint32_t*)&h;
}
__device__ __forceinline__ ull pk(float lo, float hi){ ull r; asm("mov.b64 %0,{%1,%2};":"=l"(r):"f"(lo),"f"(hi)); return r; }
__device__ __forceinline__ float2 upk(ull v){ float2 f; asm("mov.b64 {%0,%1},%2;":"=f"(f.x),"=f"(f.y):"l"(v)); return f; }
__device__ __forceinline__ ull fma2(ull a, ull b, ull c){ ull d; asm("fma.rn.f32x2 %0,%1,%2,%3;":"=l"(d):"l"(a),"l"(b),"l"(c)); return d; }

__device__ __forceinline__ void mma_f16(float* c, const uint32_t* a, const uint32_t* b) {
    asm volatile("mma.sync.aligned.m16n8k16.row.col.f32.f16.f16.f32 "
        "{%0,%1,%2,%3},{%4,%5,%6,%7},{%8,%9},{%0,%1,%2,%3};"
        : "+f"(c[0]), "+f"(c[1]), "+f"(c[2]), "+f"(c[3])
        : "r"(a[0]), "r"(a[1]), "r"(a[2]), "r"(a[3]), "r"(b[0]), "r"(b[1]));
}

// ---------------- k0: weights -> fp16 B-fragment images ----------------
__global__ void k0_prep(const float* __restrict__ Wq, const float* __restrict__ Wkv,
                        const float* __restrict__ Wp) {
    int id = blockIdx.x * 512 + threadIdx.x;   // 131072
    int n = id >> 7, kp = id & 127;
    int k = kp * 2;
    float w0, w1;
    if (n < 256)      { w0 = Wq [k*256 + n];            w1 = Wq [(k+1)*256 + n]; }
    else if (n < 512) { w0 = Wkv[k*512 + (n-256)];      w1 = Wkv[(k+1)*512 + (n-256)]; }
    else if (n < 768) { w0 = Wkv[k*512 + 256 + (n-512)];w1 = Wkv[(k+1)*512 + 256 + (n-512)]; }
    else              { w0 = Wp [k*256 + (n-768)];      w1 = Wp [(k+1)*256 + (n-768)]; }
    int nt = n >> 3, kt = kp >> 3, kw = kp & 7;
    int lane = (n & 7) * 4 + (kw & 3), s = kw >> 2;
    g_wH[nt][kt][lane][s] = hpack(w0, w1);
}

// A-fragment store: fp32 (r, 4 k's) -> fp16 image, kt-XOR swizzled
__device__ __forceinline__ void stageA1h(uint32_t* A, int r, int k4, float4 v) {
    uint32_t hw[2] = { hpack(v.x, v.y), hpack(v.z, v.w) };
    int mt = r >> 4;
    #pragma unroll
    for (int w = 0; w < 2; ++w) {
        int kp = 2 * k4 + w;
        int kt = kp >> 3, kw = kp & 7;
        int lane = (((r & 7) << 2) | (kw & 3)) ^ (kt & 7);
        int s = ((r >> 3) & 1) | ((kw >> 2) << 1);
        A[(((mt * 16 + kt) * 32 + lane) << 2) | s] = hw[w];
    }
}
// A-fragment store of one half2 (row r, even col c2)
__device__ __forceinline__ void stageAw(uint32_t* A, int r, int c2, uint32_t hv) {
    int kp = c2 >> 1;
    int kt = kp >> 3, kw = kp & 7;
    int lane = (((r & 7) << 2) | (kw & 3)) ^ (kt & 7);
    int s = ((r >> 3) & 1) | ((kw >> 2) << 1);
    A[((((r >> 4) * 16 + kt) * 32 + lane) << 2) | s] = hv;
}

// warp GEMM: m32 x n16 tile, 16 warps cover M=64 x N=128 chunk
__device__ __forceinline__ void gemm_m32n16(const uint32_t* __restrict__ sA,
                                            const uint32_t* __restrict__ sB,
                                            int mw, int nwp, int lane, float acc[2][2][4]) {
    #pragma unroll
    for (int m = 0; m < 2; ++m)
        #pragma unroll
        for (int nt = 0; nt < 2; ++nt)
            #pragma unroll
            for (int i = 0; i < 4; ++i) acc[m][nt][i] = 0.f;
    #pragma unroll
    for (int kt = 0; kt < 16; ++kt) {
        int lx = lane ^ (kt & 7);
        uint32_t a[2][4];
        #pragma unroll
        for (int m = 0; m < 2; ++m)
            *(uint4*)a[m] = *(const uint4*)(sA + ((((2 * mw + m) * 16 + kt) * 32 + lx) << 2));
        uint32_t b[2][2];
        #pragma unroll
        for (int nt = 0; nt < 2; ++nt)
            *(uint2*)b[nt] = *(const uint2*)(sB + ((((nwp * 2 + nt) * 16 + kt) * 32 + lane) << 1));
        #pragma unroll
        for (int m = 0; m < 2; ++m)
            #pragma unroll
            for (int nt = 0; nt < 2; ++nt) mma_f16(acc[m][nt], a[m], b[nt]);
    }
}

// ---------------- fused kernel ----------------
// smem map (bytes):
//   [0, 32768)        sA        x A-frag image (8192 words)   | attn work region [0,86016) reuses this
//   [32768, 98304)    sB        weight chunk (16384 words)    |   qT@0 kT@4352 vbuf@8704 P2@12800 (floats)
//   [98304, 197632)   sQKV      fp16 [64][776]  (99328 B)
//   [197632, 230400)  aoF       attn-out A-frag image (8192 words)
#define SMEM_F 230400
#define QS 776

__global__ void __launch_bounds__(512, 1)
k_fused(const float* __restrict__ x, const float* __restrict__ pos,
        const float* __restrict__ bp, float* __restrict__ out)
{
    extern __shared__ char smem[];
    uint32_t* sA   = (uint32_t*)smem;
    uint32_t* sB   = sA + 8192;
    __half*   sQKV = (__half*)(smem + 98304);
    uint32_t* aoF  = (uint32_t*)(smem + 197632);
    float* fw   = (float*)smem;
    float* qT   = fw;            // [64][68]
    float* kT   = fw + 4352;
    float* vbuf = fw + 8704;     // [64][64]
    float* P2   = fw + 12800;    // [2][64][68]

    const int t = threadIdx.x, win = blockIdx.x;
    const int b = win >> 10, nh = (win >> 5) & 31, nww = win & 31;
    const float* xb = x + (((size_t)(b * 256 + nh * 8) * 256 + nww * 8) << 8);
    const int w = t >> 5, lane = t & 31, mw = w >> 3, nwp = w & 7;

    // ---- phase 1: stage x -> sA ----
    #pragma unroll
    for (int rep = 0; rep < 8; ++rep) {
        int task = t + rep * 512;
        int r = task >> 6, k4 = task & 63;
        float4 v = *(const float4*)(xb + (size_t)(r >> 3) * 65536 + (r & 7) * 256 + k4 * 4);
        stageA1h(sA, r, k4, v);
    }

    // ---- phase 2: QKV GEMM -> sQKV ----
    for (int ch = 0; ch < 6; ++ch) {
        __syncthreads();
        const uint4* srcB = (const uint4*)&g_wH[ch * 16][0][0][0];
        uint4* dB = (uint4*)sB;
        #pragma unroll
        for (int i = 0; i < 8; ++i) dB[t + i * 512] = srcB[t + i * 512];
        __syncthreads();
        float acc[2][2][4];
        gemm_m32n16(sA, sB, mw, nwp, lane, acc);
        float sc = (ch < 2) ? QSCALE : 1.0f;
        #pragma unroll
        for (int m = 0; m < 2; ++m) {
            int row = (2 * mw + m) * 16 + (lane >> 2);
            #pragma unroll
            for (int nt = 0; nt < 2; ++nt) {
                int col = ch * 128 + (nwp * 2 + nt) * 8 + (lane & 3) * 2;
                *(__half2*)(sQKV + row * QS + col) =
                    __floats2half2_rn(acc[m][nt][0] * sc, acc[m][nt][1] * sc);
                *(__half2*)(sQKV + (row + 8) * QS + col) =
                    __floats2half2_rn(acc[m][nt][2] * sc, acc[m][nt][3] * sc);
            }
        }
    }
    __syncthreads();

    // ---- phase 3: attention (fp32 SIMT), av -> aoF ----
    const int sh = t >> 8, sidx = t & 255;
    const int sig = sidx >> 3, sjg = sidx & 7, aig = sidx >> 2, adg = sidx & 3;

    for (int hb = 0; hb < 4; ++hb) {
        #pragma unroll
        for (int rep = 0; rep < 2; ++rep) {
            int task = t + rep * 512, row = task >> 4, c4 = task & 15;
            const __half* s = sQKV + row * QS + hb * 64 + c4 * 4;
            uint2 qw = *(const uint2*)(s);
            uint2 kw = *(const uint2*)(s + 256);
            uint2 vw = *(const uint2*)(s + 512);
            float2 qa = __half22float2(*(__half2*)&qw.x), qb = __half22float2(*(__half2*)&qw.y);
            float2 ka = __half22float2(*(__half2*)&kw.x), kb = __half22float2(*(__half2*)&kw.y);
            float2 va = __half22float2(*(__half2*)&vw.x), vb2 = __half22float2(*(__half2*)&vw.y);
            int c = c4 * 4;
            qT[c*68+row]=qa.x; qT[(c+1)*68+row]=qa.y; qT[(c+2)*68+row]=qb.x; qT[(c+3)*68+row]=qb.y;
            kT[c*68+row]=ka.x; kT[(c+1)*68+row]=ka.y; kT[(c+2)*68+row]=kb.x; kT[(c+3)*68+row]=kb.y;
            *(float4*)(vbuf + row * 64 + c) = make_float4(va.x, va.y, vb2.x, vb2.y);
        }
        __syncthreads();
        {   // sim + softmax
            const int hq = sh * 32;
            ull s0[4] = {0,0,0,0}, s1[4] = {0,0,0,0};
            #pragma unroll 4
            for (int d = 0; d < 32; ++d) {
                float2 qv = *(const float2*)(qT + (hq + d) * 68 + sig * 2);
                ull q0 = pk(qv.x, qv.x), q1 = pk(qv.y, qv.y);
                const float* kr = kT + (hq + d) * 68 + sjg * 8;
                ulonglong2 ka = *(const ulonglong2*)(kr);
                ulonglong2 kb = *(const ulonglong2*)(kr + 4);
                s0[0]=fma2(q0,ka.x,s0[0]); s1[0]=fma2(q1,ka.x,s1[0]);
                s0[1]=fma2(q0,ka.y,s0[1]); s1[1]=fma2(q1,ka.y,s1[1]);
                s0[2]=fma2(q0,kb.x,s0[2]); s1[2]=fma2(q1,kb.x,s1[2]);
                s0[3]=fma2(q0,kb.y,s0[3]); s1[3]=fma2(q1,kb.y,s1[3]);
            }
            const int i0 = sig * 2, hcur = hb * 2 + sh;
            const float* pp = pos + hcur * 4096 + i0 * 64 + sjg * 8;
            float sv0[8], sv1[8];
            #pragma unroll
            for (int p = 0; p < 4; ++p) {
                float2 f0 = upk(s0[p]); sv0[p*2]=f0.x; sv0[p*2+1]=f0.y;
                float2 f1 = upk(s1[p]); sv1[p*2]=f1.x; sv1[p*2+1]=f1.y;
            }
            #pragma unroll
            for (int jj = 0; jj < 8; ++jj) { sv0[jj] += __ldg(pp + jj); sv1[jj] += __ldg(pp + 64 + jj); }
            float m0 = sv0[0], m1 = sv1[0];
            #pragma unroll
            for (int jj = 1; jj < 8; ++jj) { m0 = fmaxf(m0, sv0[jj]); m1 = fmaxf(m1, sv1[jj]); }
            #pragma unroll
            for (int o = 1; o < 8; o <<= 1) {
                m0 = fmaxf(m0, __shfl_xor_sync(0xffffffffu, m0, o));
                m1 = fmaxf(m1, __shfl_xor_sync(0xffffffffu, m1, o));
            }
            float su0 = 0.f, su1 = 0.f;
            #pragma unroll
            for (int jj = 0; jj < 8; ++jj) {
                sv0[jj] = __expf(sv0[jj] - m0); su0 += sv0[jj];
                sv1[jj] = __expf(sv1[jj] - m1); su1 += sv1[jj];
            }
            #pragma unroll
            for (int o = 1; o < 8; o <<= 1) {
                su0 += __shfl_xor_sync(0xffffffffu, su0, o);
                su1 += __shfl_xor_sync(0xffffffffu, su1, o);
            }
            float inv0 = 1.f / su0, inv1 = 1.f / su1;
            float* pr = P2 + sh * 4352 + i0 * 68 + sjg * 8;
            *(float4*)(pr)      = make_float4(sv0[0]*inv0, sv0[1]*inv0, sv0[2]*inv0, sv0[3]*inv0);
            *(float4*)(pr+4)    = make_float4(sv0[4]*inv0, sv0[5]*inv0, sv0[6]*inv0, sv0[7]*inv0);
            *(float4*)(pr+68)   = make_float4(sv1[0]*inv1, sv1[1]*inv1, sv1[2]*inv1, sv1[3]*inv1);
            *(float4*)(pr+68+4) = make_float4(sv1[4]*inv1, sv1[5]*inv1, sv1[6]*inv1, sv1[7]*inv1);
        }
        __syncthreads();
        {   // av -> aoF (fp16 A-fragment image; same rounding k3 applied before)
            ull o[4] = {0,0,0,0};
            const float* pr = P2 + sh * 4352 + aig * 68;
            const float* vp = vbuf + sh * 32 + adg * 8;
            #pragma unroll 4
            for (int j = 0; j < 64; ++j) {
                float p = pr[j]; ull pb = pk(p, p);
                ulonglong2 va = *(const ulonglong2*)(vp + j * 64);
                ulonglong2 vb2 = *(const ulonglong2*)(vp + j * 64 + 4);
                o[0]=fma2(pb,va.x,o[0]); o[1]=fma2(pb,va.y,o[1]);
                o[2]=fma2(pb,vb2.x,o[2]); o[3]=fma2(pb,vb2.y,o[3]);
            }
            int dbase = (hb * 2 + sh) * 32 + adg * 8;
            #pragma unroll
            for (int p = 0; p < 4; ++p) {
                float2 f = upk(o[p]);
                stageAw(aoF, aig, dbase + 2 * p, hpack(f.x, f.y));
            }
        }
        __syncthreads();
    }

    // ---- phase 4: projection GEMM + bias + un-window ----
    float* obase = out + (((size_t)(b * 256 + nh * 8) * 256 + nww * 8) << 8);
    for (int ch = 0; ch < 2; ++ch) {
        __syncthreads();
        const uint4* srcB = (const uint4*)&g_wH[96 + ch * 16][0][0][0];
        uint4* dB = (uint4*)sB;
        #pragma unroll
        for (int i = 0; i < 8; ++i) dB[t + i * 512] = srcB[t + i * 512];
        __syncthreads();
        float acc[2][2][4];
        gemm_m32n16(aoF, sB, mw, nwp, lane, acc);
        #pragma unroll
        for (int m = 0; m < 2; ++m) {
            int row = (2 * mw + m) * 16 + (lane >> 2);
            #pragma unroll
            for (int nt = 0; nt < 2; ++nt) {
                int c = ch * 128 + (nwp * 2 + nt) * 8 + (lane & 3) * 2;
                float2 bias = *(const float2*)(bp + c);
                int r0 = row, r1 = row + 8;
                *(float2*)(obase + (r0 >> 3) * 65536 + (r0 & 7) * 256 + c) =
                    make_float2(acc[m][nt][0] + bias.x, acc[m][nt][1] + bias.y);
                *(float2*)(obase + (r1 >> 3) * 65536 + (r1 & 7) * 256 + c) =
                    make_float2(acc[m][nt][2] + bias.x, acc[m][nt][3] + bias.y);
            }
        }
    }
}

extern "C" void kernel_launch(void* const* d_in, const int* in_sizes, int n_in,
                              void* d_out, int out_size)
{
    const float* x   = (const float*)d_in[0];
    const float* Wq  = (const float*)d_in[1];
    const float* Wkv = (const float*)d_in[2];
    const float* pos = (const float*)d_in[3];
    const float* Wp  = (const float*)d_in[4];
    const float* bp  = (const float*)d_in[5];
    float* out = (float*)d_out;

    cudaFuncSetAttribute(k_fused, cudaFuncAttributeMaxDynamicSharedMemorySize, SMEM_F);

    k0_prep<<<256, 512>>>(Wq, Wkv, Wp);
    k_fused<<<4096, 512, SMEM_F>>>(x, pos, bp, out);
}

// round 13
// speedup vs baseline: 1.2746x; 1.2746x over previous
#include <cuda_runtime.h>
#include <cuda_fp16.h>
#include <cstdint>

typedef unsigned long long ull;

#define QSCALE 0.17677669529663687f

// fp16 B-fragment images, n ordering: [0,256)=Wq, [256,512)=Wkv.k, [512,768)=Wkv.v, [768,1024)=Wp
__device__ uint32_t g_wH[128][16][32][2];

// ---------------- helpers ----------------
__device__ __forceinline__ uint32_t hpack(float a, float b) {
    __half2 h = __floats2half2_rn(a, b);
    return *(uint32_t*)&h;
}
__device__ __forceinline__ ull pk(float lo, float hi){ ull r; asm("mov.b64 %0,{%1,%2};":"=l"(r):"f"(lo),"f"(hi)); return r; }
__device__ __forceinline__ float2 upk(ull v){ float2 f; asm("mov.b64 {%0,%1},%2;":"=f"(f.x),"=f"(f.y):"l"(v)); return f; }
__device__ __forceinline__ ull fma2(ull a, ull b, ull c){ ull d; asm("fma.rn.f32x2 %0,%1,%2,%3;":"=l"(d):"l"(a),"l"(b),"l"(c)); return d; }
__device__ __forceinline__ ull pkh2(uint32_t h2) {           // half2 -> packed f32x2
    float2 f = __half22float2(*(__half2*)&h2);
    return pk(f.x, f.y);
}

__device__ __forceinline__ void mma_f16(float* c, const uint32_t* a, const uint32_t* b) {
    asm volatile("mma.sync.aligned.m16n8k16.row.col.f32.f16.f16.f32 "
        "{%0,%1,%2,%3},{%4,%5,%6,%7},{%8,%9},{%0,%1,%2,%3};"
        : "+f"(c[0]), "+f"(c[1]), "+f"(c[2]), "+f"(c[3])
        : "r"(a[0]), "r"(a[1]), "r"(a[2]), "r"(a[3]), "r"(b[0]), "r"(b[1]));
}

// ---------------- k0: weights -> fp16 B-fragment images ----------------
__global__ void k0_prep(const float* __restrict__ Wq, const float* __restrict__ Wkv,
                        const float* __restrict__ Wp) {
    int id = blockIdx.x * 512 + threadIdx.x;   // 131072
    int n = id >> 7, kp = id & 127;
    int k = kp * 2;
    float w0, w1;
    if (n < 256)      { w0 = Wq [k*256 + n];            w1 = Wq [(k+1)*256 + n]; }
    else if (n < 512) { w0 = Wkv[k*512 + (n-256)];      w1 = Wkv[(k+1)*512 + (n-256)]; }
    else if (n < 768) { w0 = Wkv[k*512 + 256 + (n-512)];w1 = Wkv[(k+1)*512 + 256 + (n-512)]; }
    else              { w0 = Wp [k*256 + (n-768)];      w1 = Wp [(k+1)*256 + (n-768)]; }
    int nt = n >> 3, kt = kp >> 3, kw = kp & 7;
    int lane = (n & 7) * 4 + (kw & 3), s = kw >> 2;
    g_wH[nt][kt][lane][s] = hpack(w0, w1);
}

// A-fragment store: fp32 (r, 4 k's) -> fp16 image, kt-XOR swizzled
__device__ __forceinline__ void stageA1h(uint32_t* A, int r, int k4, float4 v) {
    uint32_t hw[2] = { hpack(v.x, v.y), hpack(v.z, v.w) };
    int mt = r >> 4;
    #pragma unroll
    for (int w = 0; w < 2; ++w) {
        int kp = 2 * k4 + w;
        int kt = kp >> 3, kw = kp & 7;
        int lane = (((r & 7) << 2) | (kw & 3)) ^ (kt & 7);
        int s = ((r >> 3) & 1) | ((kw >> 2) << 1);
        A[(((mt * 16 + kt) * 32 + lane) << 2) | s] = hw[w];
    }
}
// A-fragment store of one half2 (row r, even col c2)
__device__ __forceinline__ void stageAw(uint32_t* A, int r, int c2, uint32_t hv) {
    int kp = c2 >> 1;
    int kt = kp >> 3, kw = kp & 7;
    int lane = (((r & 7) << 2) | (kw & 3)) ^ (kt & 7);
    int s = ((r >> 3) & 1) | ((kw >> 2) << 1);
    A[((((r >> 4) * 16 + kt) * 32 + lane) << 2) | s] = hv;
}

// warp GEMM: m32 x n16 tile, 16 warps cover M=64 x N=128 chunk
__device__ __forceinline__ void gemm_m32n16(const uint32_t* __restrict__ sA,
                                            const uint32_t* __restrict__ sB,
                                            int mw, int nwp, int lane, float acc[2][2][4]) {
    #pragma unroll
    for (int m = 0; m < 2; ++m)
        #pragma unroll
        for (int nt = 0; nt < 2; ++nt)
            #pragma unroll
            for (int i = 0; i < 4; ++i) acc[m][nt][i] = 0.f;
    #pragma unroll
    for (int kt = 0; kt < 16; ++kt) {
        int lx = lane ^ (kt & 7);
        uint32_t a[2][4];
        #pragma unroll
        for (int m = 0; m < 2; ++m)
            *(uint4*)a[m] = *(const uint4*)(sA + ((((2 * mw + m) * 16 + kt) * 32 + lx) << 2));
        uint32_t b[2][2];
        #pragma unroll
        for (int nt = 0; nt < 2; ++nt)
            *(uint2*)b[nt] = *(const uint2*)(sB + ((((nwp * 2 + nt) * 16 + kt) * 32 + lane) << 1));
        #pragma unroll
        for (int m = 0; m < 2; ++m)
            #pragma unroll
            for (int nt = 0; nt < 2; ++nt) mma_f16(acc[m][nt], a[m], b[nt]);
    }
}

// ---------------- fused kernel v2 ----------------
// smem map (bytes):
//   [0, 32768)        sA   x A-frag image  -> reused as aoF (attn-out frag image)
//   [32768, 98304)    sB   weight chunk    -> P2 (fp32 [2][64][68]) during attention
//   [98304, 135168)   qTh  fp16 [256 d][72 rows]
//   [135168, 172032)  kTh  fp16 [256 d][72 rows]
//   [172032, 205824)  vbuf fp16 [64 rows][264 d]
#define SMEM_F 205824
#define QTS 72
#define VS  264

__global__ void __launch_bounds__(512, 1)
k_fused(const float* __restrict__ x, const float* __restrict__ pos,
        const float* __restrict__ bp, float* __restrict__ out)
{
    extern __shared__ char smem[];
    uint32_t* sA  = (uint32_t*)smem;              // also aoF
    uint32_t* sB  = sA + 8192;
    float*    P2  = (float*)(smem + 32768);       // overlays sB during attention
    __half*   qTh = (__half*)(smem + 98304);
    __half*   kTh = (__half*)(smem + 135168);
    __half*   vbuf= (__half*)(smem + 172032);

    const int t = threadIdx.x, win = blockIdx.x;
    const int b = win >> 10, nh = (win >> 5) & 31, nww = win & 31;
    const float* xb = x + (((size_t)(b * 256 + nh * 8) * 256 + nww * 8) << 8);
    const int w = t >> 5, lane = t & 31, mw = w >> 3, nwp = w & 7;

    // ---- phase 1: stage x -> sA ----
    #pragma unroll
    for (int rep = 0; rep < 8; ++rep) {
        int task = t + rep * 512;
        int r = task >> 6, k4 = task & 63;
        float4 v = *(const float4*)(xb + (size_t)(r >> 3) * 65536 + (r & 7) * 256 + k4 * 4);
        stageA1h(sA, r, k4, v);
    }

    // ---- phase 2: QKV GEMM, epilogue writes qTh/kTh/vbuf directly ----
    for (int ch = 0; ch < 6; ++ch) {
        __syncthreads();
        const uint4* srcB = (const uint4*)&g_wH[ch * 16][0][0][0];
        uint4* dB = (uint4*)sB;
        #pragma unroll
        for (int i = 0; i < 8; ++i) dB[t + i * 512] = srcB[t + i * 512];
        __syncthreads();
        float acc[2][2][4];
        gemm_m32n16(sA, sB, mw, nwp, lane, acc);
        #pragma unroll
        for (int m = 0; m < 2; ++m) {
            int row = (2 * mw + m) * 16 + (lane >> 2);
            #pragma unroll
            for (int nt = 0; nt < 2; ++nt) {
                int cc = (nwp * 2 + nt) * 8 + (lane & 3) * 2;
                if (ch < 2) {            // q (scaled), d-major
                    int d0 = ch * 128 + cc;
                    qTh[d0 * QTS + row]           = __float2half_rn(acc[m][nt][0] * QSCALE);
                    qTh[(d0 + 1) * QTS + row]     = __float2half_rn(acc[m][nt][1] * QSCALE);
                    qTh[d0 * QTS + row + 8]       = __float2half_rn(acc[m][nt][2] * QSCALE);
                    qTh[(d0 + 1) * QTS + row + 8] = __float2half_rn(acc[m][nt][3] * QSCALE);
                } else if (ch < 4) {     // k, d-major
                    int d0 = (ch - 2) * 128 + cc;
                    kTh[d0 * QTS + row]           = __float2half_rn(acc[m][nt][0]);
                    kTh[(d0 + 1) * QTS + row]     = __float2half_rn(acc[m][nt][1]);
                    kTh[d0 * QTS + row + 8]       = __float2half_rn(acc[m][nt][2]);
                    kTh[(d0 + 1) * QTS + row + 8] = __float2half_rn(acc[m][nt][3]);
                } else {                 // v, row-major
                    int d0 = (ch - 4) * 128 + cc;
                    *(__half2*)(vbuf + row * VS + d0) =
                        __floats2half2_rn(acc[m][nt][0], acc[m][nt][1]);
                    *(__half2*)(vbuf + (row + 8) * VS + d0) =
                        __floats2half2_rn(acc[m][nt][2], acc[m][nt][3]);
                }
            }
        }
    }
    __syncthreads();

    // ---- phase 3: attention (fp32 SIMT), av -> aoF (=sA region) ----
    const int sh = t >> 8, sidx = t & 255;
    const int sig = sidx >> 3, sjg = sidx & 7, aig = sidx >> 2, adg = sidx & 3;

    for (int hb = 0; hb < 4; ++hb) {
        const int hcur = hb * 2 + sh;
        {   // sim + softmax
            ull s0[4] = {0,0,0,0}, s1[4] = {0,0,0,0};
            #pragma unroll 4
            for (int d = 0; d < 32; ++d) {
                const int dg = hcur * 32 + d;
                float2 qv = __half22float2(*(const __half2*)(qTh + dg * QTS + sig * 2));
                ull q0 = pk(qv.x, qv.x), q1 = pk(qv.y, qv.y);
                uint4 kw4 = *(const uint4*)(kTh + dg * QTS + sjg * 8);
                ull ka0 = pkh2(kw4.x), ka1 = pkh2(kw4.y);
                ull ka2 = pkh2(kw4.z), ka3 = pkh2(kw4.w);
                s0[0]=fma2(q0,ka0,s0[0]); s1[0]=fma2(q1,ka0,s1[0]);
                s0[1]=fma2(q0,ka1,s0[1]); s1[1]=fma2(q1,ka1,s1[1]);
                s0[2]=fma2(q0,ka2,s0[2]); s1[2]=fma2(q1,ka2,s1[2]);
                s0[3]=fma2(q0,ka3,s0[3]); s1[3]=fma2(q1,ka3,s1[3]);
            }
            const int i0 = sig * 2;
            const float* pp = pos + hcur * 4096 + i0 * 64 + sjg * 8;
            float sv0[8], sv1[8];
            #pragma unroll
            for (int p = 0; p < 4; ++p) {
                float2 f0 = upk(s0[p]); sv0[p*2]=f0.x; sv0[p*2+1]=f0.y;
                float2 f1 = upk(s1[p]); sv1[p*2]=f1.x; sv1[p*2+1]=f1.y;
            }
            #pragma unroll
            for (int jj = 0; jj < 8; ++jj) { sv0[jj] += __ldg(pp + jj); sv1[jj] += __ldg(pp + 64 + jj); }
            float m0 = sv0[0], m1 = sv1[0];
            #pragma unroll
            for (int jj = 1; jj < 8; ++jj) { m0 = fmaxf(m0, sv0[jj]); m1 = fmaxf(m1, sv1[jj]); }
            #pragma unroll
            for (int o = 1; o < 8; o <<= 1) {
                m0 = fmaxf(m0, __shfl_xor_sync(0xffffffffu, m0, o));
                m1 = fmaxf(m1, __shfl_xor_sync(0xffffffffu, m1, o));
            }
            float su0 = 0.f, su1 = 0.f;
            #pragma unroll
            for (int jj = 0; jj < 8; ++jj) {
                sv0[jj] = __expf(sv0[jj] - m0); su0 += sv0[jj];
                sv1[jj] = __expf(sv1[jj] - m1); su1 += sv1[jj];
            }
            #pragma unroll
            for (int o = 1; o < 8; o <<= 1) {
                su0 += __shfl_xor_sync(0xffffffffu, su0, o);
                su1 += __shfl_xor_sync(0xffffffffu, su1, o);
            }
            float inv0 = 1.f / su0, inv1 = 1.f / su1;
            float* pr = P2 + sh * 4352 + i0 * 68 + sjg * 8;
            *(float4*)(pr)      = make_float4(sv0[0]*inv0, sv0[1]*inv0, sv0[2]*inv0, sv0[3]*inv0);
            *(float4*)(pr+4)    = make_float4(sv0[4]*inv0, sv0[5]*inv0, sv0[6]*inv0, sv0[7]*inv0);
            *(float4*)(pr+68)   = make_float4(sv1[0]*inv1, sv1[1]*inv1, sv1[2]*inv1, sv1[3]*inv1);
            *(float4*)(pr+68+4) = make_float4(sv1[4]*inv1, sv1[5]*inv1, sv1[6]*inv1, sv1[7]*inv1);
        }
        __syncthreads();
        {   // av -> aoF
            const int dbase = hcur * 32 + adg * 8;
            ull o[4] = {0,0,0,0};
            const float* pr = P2 + sh * 4352 + aig * 68;
            const __half* vp = vbuf + dbase;
            #pragma unroll 4
            for (int j = 0; j < 64; ++j) {
                float p = pr[j]; ull pb = pk(p, p);
                uint4 vw4 = *(const uint4*)(vp + j * VS);
                o[0]=fma2(pb, pkh2(vw4.x), o[0]);
                o[1]=fma2(pb, pkh2(vw4.y), o[1]);
                o[2]=fma2(pb, pkh2(vw4.z), o[2]);
                o[3]=fma2(pb, pkh2(vw4.w), o[3]);
            }
            #pragma unroll
            for (int p = 0; p < 4; ++p) {
                float2 f = upk(o[p]);
                stageAw(sA, aig, dbase + 2 * p, hpack(f.x, f.y));
            }
        }
        __syncthreads();
    }

    // ---- phase 4: projection GEMM + bias + un-window ----
    float* obase = out + (((size_t)(b * 256 + nh * 8) * 256 + nww * 8) << 8);
    for (int ch = 0; ch < 2; ++ch) {
        __syncthreads();
        const uint4* srcB = (const uint4*)&g_wH[96 + ch * 16][0][0][0];
        uint4* dB = (uint4*)sB;
        #pragma unroll
        for (int i = 0; i < 8; ++i) dB[t + i * 512] = srcB[t + i * 512];
        __syncthreads();
        float acc[2][2][4];
        gemm_m32n16(sA, sB, mw, nwp, lane, acc);
        #pragma unroll
        for (int m = 0; m < 2; ++m) {
            int row = (2 * mw + m) * 16 + (lane >> 2);
            #pragma unroll
            for (int nt = 0; nt < 2; ++nt) {
                int c = ch * 128 + (nwp * 2 + nt) * 8 + (lane & 3) * 2;
                float2 bias = *(const float2*)(bp + c);
                int r0 = row, r1 = row + 8;
                *(float2*)(obase + (r0 >> 3) * 65536 + (r0 & 7) * 256 + c) =
                    make_float2(acc[m][nt][0] + bias.x, acc[m][nt][1] + bias.y);
                *(float2*)(obase + (r1 >> 3) * 65536 + (r1 & 7) * 256 + c) =
                    make_float2(acc[m][nt][2] + bias.x, acc[m][nt][3] + bias.y);
            }
        }
    }
}

extern "C" void kernel_launch(void* const* d_in, const int* in_sizes, int n_in,
                              void* d_out, int out_size)
{
    const float* x   = (const float*)d_in[0];
    const float* Wq  = (const float*)d_in[1];
    const float* Wkv = (const float*)d_in[2];
    const float* pos = (const float*)d_in[3];
    const float* Wp  = (const float*)d_in[4];
    const float* bp  = (const float*)d_in[5];
    float* out = (float*)d_out;

    cudaFuncSetAttribute(k_fused, cudaFuncAttributeMaxDynamicSharedMemorySize, SMEM_F);

    k0_prep<<<256, 512>>>(Wq, Wkv, Wp);
    k_fused<<<4096, 512, SMEM_F>>>(x, pos, bp, out);
}

// round 15
// speedup vs baseline: 2.3436x; 1.8387x over previous
#include <cuda_runtime.h>
#include <cuda_fp16.h>
#include <cstdint>

typedef unsigned long long ull;

#define QSCALE 0.17677669529663687f

// fp16 B-fragment images, n ordering: [0,256)=Wq, [256,512)=Wkv.k, [512,768)=Wkv.v, [768,1024)=Wp
__device__ uint32_t g_wH[128][16][32][2];

// ---------------- helpers ----------------
__device__ __forceinline__ uint32_t hpack(float a, float b) {
    __half2 h = __floats2half2_rn(a, b);
    return *(uint32_t*)&h;
}

__device__ __forceinline__ void mma_f16(float* c, const uint32_t* a, const uint32_t* b) {
    asm volatile("mma.sync.aligned.m16n8k16.row.col.f32.f16.f16.f32 "
        "{%0,%1,%2,%3},{%4,%5,%6,%7},{%8,%9},{%0,%1,%2,%3};"
        : "+f"(c[0]), "+f"(c[1]), "+f"(c[2]), "+f"(c[3])
        : "r"(a[0]), "r"(a[1]), "r"(a[2]), "r"(a[3]), "r"(b[0]), "r"(b[1]));
}

// ---------------- k0: weights -> fp16 B-fragment images ----------------
__global__ void k0_prep(const float* __restrict__ Wq, const float* __restrict__ Wkv,
                        const float* __restrict__ Wp) {
    int id = blockIdx.x * 512 + threadIdx.x;   // 131072
    int n = id >> 7, kp = id & 127;
    int k = kp * 2;
    float w0, w1;
    if (n < 256)      { w0 = Wq [k*256 + n];            w1 = Wq [(k+1)*256 + n]; }
    else if (n < 512) { w0 = Wkv[k*512 + (n-256)];      w1 = Wkv[(k+1)*512 + (n-256)]; }
    else if (n < 768) { w0 = Wkv[k*512 + 256 + (n-512)];w1 = Wkv[(k+1)*512 + 256 + (n-512)]; }
    else              { w0 = Wp [k*256 + (n-768)];      w1 = Wp [(k+1)*256 + (n-768)]; }
    int nt = n >> 3, kt = kp >> 3, kw = kp & 7;
    int lane = (n & 7) * 4 + (kw & 3), s = kw >> 2;
    g_wH[nt][kt][lane][s] = hpack(w0, w1);
}

// A-fragment store: fp32 (r, 4 k's) -> fp16 image, kt-XOR swizzled
__device__ __forceinline__ void stageA1h(uint32_t* A, int r, int k4, float4 v) {
    uint32_t hw[2] = { hpack(v.x, v.y), hpack(v.z, v.w) };
    int mt = r >> 4;
    #pragma unroll
    for (int w = 0; w < 2; ++w) {
        int kp = 2 * k4 + w;
        int kt = kp >> 3, kw = kp & 7;
        int lane = (((r & 7) << 2) | (kw & 3)) ^ (kt & 7);
        int s = ((r >> 3) & 1) | ((kw >> 2) << 1);
        A[(((mt * 16 + kt) * 32 + lane) << 2) | s] = hw[w];
    }
}
// A-fragment store of one half2 (row r, even col c2)
__device__ __forceinline__ void stageAw(uint32_t* A, int r, int c2, uint32_t hv) {
    int kp = c2 >> 1;
    int kt = kp >> 3, kw = kp & 7;
    int lane = (((r & 7) << 2) | (kw & 3)) ^ (kt & 7);
    int s = ((r >> 3) & 1) | ((kw >> 2) << 1);
    A[((((r >> 4) * 16 + kt) * 32 + lane) << 2) | s] = hv;
}

// warp GEMM: m32 x n16 tile, 16 warps cover M=64 x N=128 chunk
__device__ __forceinline__ void gemm_m32n16(const uint32_t* __restrict__ sA,
                                            const uint32_t* __restrict__ sB,
                                            int mw, int nwp, int lane, float acc[2][2][4]) {
    #pragma unroll
    for (int m = 0; m < 2; ++m)
        #pragma unroll
        for (int nt = 0; nt < 2; ++nt)
            #pragma unroll
            for (int i = 0; i < 4; ++i) acc[m][nt][i] = 0.f;
    #pragma unroll
    for (int kt = 0; kt < 16; ++kt) {
        int lx = lane ^ (kt & 7);
        uint32_t a[2][4];
        #pragma unroll
        for (int m = 0; m < 2; ++m)
            *(uint4*)a[m] = *(const uint4*)(sA + ((((2 * mw + m) * 16 + kt) * 32 + lx) << 2));
        uint32_t b[2][2];
        #pragma unroll
        for (int nt = 0; nt < 2; ++nt)
            *(uint2*)b[nt] = *(const uint2*)(sB + ((((nwp * 2 + nt) * 16 + kt) * 32 + lane) << 1));
        #pragma unroll
        for (int m = 0; m < 2; ++m)
            #pragma unroll
            for (int nt = 0; nt < 2; ++nt) mma_f16(acc[m][nt], a[m], b[nt]);
    }
}

// ---------------- fused kernel v3: all-MMA ----------------
// smem map (bytes):
//   [0, 32768)        sA   x A-frag image  -> reused as aoF (attn-out frag image)
//   [32768, 98304)    sB   weight chunk
//   [98304, 132096)   qh   fp16 [64 rows][264 d]  (q, scaled)
//   [132096, 165888)  kh   fp16 [64 rows][264 d]
//   [165888, 202752)  vT   fp16 [256 d][72 rows]
#define SMEM_F 202752
#define QKS 264
#define VTS 72

__global__ void __launch_bounds__(512, 1)
k_fused(const float* __restrict__ x, const float* __restrict__ pos,
        const float* __restrict__ bp, float* __restrict__ out)
{
    extern __shared__ char smem[];
    uint32_t* sA = (uint32_t*)smem;               // also aoF
    uint32_t* sB = sA + 8192;
    __half*   qh = (__half*)(smem + 98304);
    __half*   kh = (__half*)(smem + 132096);
    __half*   vT = (__half*)(smem + 165888);

    const int t = threadIdx.x, win = blockIdx.x;
    const int b = win >> 10, nh = (win >> 5) & 31, nww = win & 31;
    const float* xb = x + (((size_t)(b * 256 + nh * 8) * 256 + nww * 8) << 8);
    const int w = t >> 5, lane = t & 31, mw = w >> 3, nwp = w & 7;
    const int gid = lane >> 2, tg = lane & 3;

    // ---- phase 1: stage x -> sA ----
    #pragma unroll
    for (int rep = 0; rep < 8; ++rep) {
        int task = t + rep * 512;
        int r = task >> 6, k4 = task & 63;
        float4 v = *(const float4*)(xb + (size_t)(r >> 3) * 65536 + (r & 7) * 256 + k4 * 4);
        stageA1h(sA, r, k4, v);
    }

    // ---- phase 2: QKV GEMM; epilogue writes qh/kh (row-major) and vT (d-major) ----
    for (int ch = 0; ch < 6; ++ch) {
        __syncthreads();
        const uint4* srcB = (const uint4*)&g_wH[ch * 16][0][0][0];
        uint4* dB = (uint4*)sB;
        #pragma unroll
        for (int i = 0; i < 8; ++i) dB[t + i * 512] = srcB[t + i * 512];
        __syncthreads();
        float acc[2][2][4];
        gemm_m32n16(sA, sB, mw, nwp, lane, acc);
        #pragma unroll
        for (int m = 0; m < 2; ++m) {
            int row = (2 * mw + m) * 16 + gid;
            #pragma unroll
            for (int nt = 0; nt < 2; ++nt) {
                int cc = (nwp * 2 + nt) * 8 + tg * 2;
                if (ch < 2) {            // q row-major, scaled
                    int d0 = ch * 128 + cc;
                    *(uint32_t*)(qh + row * QKS + d0) =
                        hpack(acc[m][nt][0] * QSCALE, acc[m][nt][1] * QSCALE);
                    *(uint32_t*)(qh + (row + 8) * QKS + d0) =
                        hpack(acc[m][nt][2] * QSCALE, acc[m][nt][3] * QSCALE);
                } else if (ch < 4) {     // k row-major
                    int d0 = (ch - 2) * 128 + cc;
                    *(uint32_t*)(kh + row * QKS + d0) = hpack(acc[m][nt][0], acc[m][nt][1]);
                    *(uint32_t*)(kh + (row + 8) * QKS + d0) = hpack(acc[m][nt][2], acc[m][nt][3]);
                } else {                 // v d-major
                    int d0 = (ch - 4) * 128 + cc;
                    vT[d0 * VTS + row]           = __float2half_rn(acc[m][nt][0]);
                    vT[(d0 + 1) * VTS + row]     = __float2half_rn(acc[m][nt][1]);
                    vT[d0 * VTS + row + 8]       = __float2half_rn(acc[m][nt][2]);
                    vT[(d0 + 1) * VTS + row + 8] = __float2half_rn(acc[m][nt][3]);
                }
            }
        }
    }
    __syncthreads();

    // ---- phase 3: attention, fully on tensor cores ----
    // 32 tasks = 8 heads x 4 rowblocks; each warp runs 2.
    #pragma unroll
    for (int it = 0; it < 2; ++it) {
        int task = w + 16 * it;
        int h = task >> 2, rb = task & 3;
        int r0 = rb * 16;

        // Q A-fragments (k = d, 2 k16 steps)
        uint32_t qa[2][4];
        const __half* qrow = qh + (r0 + gid) * QKS + h * 32 + tg * 2;
        #pragma unroll
        for (int ks = 0; ks < 2; ++ks) {
            qa[ks][0] = *(const uint32_t*)(qrow + ks * 16);
            qa[ks][1] = *(const uint32_t*)(qrow + 8 * QKS + ks * 16);
            qa[ks][2] = *(const uint32_t*)(qrow + ks * 16 + 8);
            qa[ks][3] = *(const uint32_t*)(qrow + 8 * QKS + ks * 16 + 8);
        }

        // S = Q K^T  (m16 x n64, 8 n-tiles)
        float ss[8][4];
        #pragma unroll
        for (int nt = 0; nt < 8; ++nt) {
            ss[nt][0] = ss[nt][1] = ss[nt][2] = ss[nt][3] = 0.f;
            const __half* krow = kh + (nt * 8 + gid) * QKS + h * 32 + tg * 2;
            #pragma unroll
            for (int ks = 0; ks < 2; ++ks) {
                uint32_t kb[2] = { *(const uint32_t*)(krow + ks * 16),
                                   *(const uint32_t*)(krow + ks * 16 + 8) };
                mma_f16(ss[nt], qa[ks], kb);
            }
        }

        // + pos
        const float* pb = pos + h * 4096 + (r0 + gid) * 64 + tg * 2;
        #pragma unroll
        for (int nt = 0; nt < 8; ++nt) {
            float2 p0 = __ldg((const float2*)(pb + nt * 8));
            float2 p1 = __ldg((const float2*)(pb + 8 * 64 + nt * 8));
            ss[nt][0] += p0.x; ss[nt][1] += p0.y;
            ss[nt][2] += p1.x; ss[nt][3] += p1.y;
        }

        // softmax (rows r0+gid and r0+gid+8), reduce over regs + 4-lane group
        float mA = ss[0][0], mB = ss[0][2];
        #pragma unroll
        for (int nt = 0; nt < 8; ++nt) {
            mA = fmaxf(mA, fmaxf(ss[nt][0], ss[nt][1]));
            mB = fmaxf(mB, fmaxf(ss[nt][2], ss[nt][3]));
        }
        #pragma unroll
        for (int o = 1; o < 4; o <<= 1) {
            mA = fmaxf(mA, __shfl_xor_sync(0xffffffffu, mA, o));
            mB = fmaxf(mB, __shfl_xor_sync(0xffffffffu, mB, o));
        }
        float sA_ = 0.f, sB_ = 0.f;
        #pragma unroll
        for (int nt = 0; nt < 8; ++nt) {
            ss[nt][0] = __expf(ss[nt][0] - mA); sA_ += ss[nt][0];
            ss[nt][1] = __expf(ss[nt][1] - mA); sA_ += ss[nt][1];
            ss[nt][2] = __expf(ss[nt][2] - mB); sB_ += ss[nt][2];
            ss[nt][3] = __expf(ss[nt][3] - mB); sB_ += ss[nt][3];
        }
        #pragma unroll
        for (int o = 1; o < 4; o <<= 1) {
            sA_ += __shfl_xor_sync(0xffffffffu, sA_, o);
            sB_ += __shfl_xor_sync(0xffffffffu, sB_, o);
        }
        float invA = 1.f / sA_, invB = 1.f / sB_;

        // P (normalized, fp16) as A-fragments for PV: 4 k16 steps from n-tile pairs
        uint32_t pa[4][4];
        #pragma unroll
        for (int kk = 0; kk < 4; ++kk) {
            pa[kk][0] = hpack(ss[2*kk][0]   * invA, ss[2*kk][1]   * invA);
            pa[kk][1] = hpack(ss[2*kk][2]   * invB, ss[2*kk][3]   * invB);
            pa[kk][2] = hpack(ss[2*kk+1][0] * invA, ss[2*kk+1][1] * invA);
            pa[kk][3] = hpack(ss[2*kk+1][2] * invB, ss[2*kk+1][3] * invB);
        }

        // O = P V  (m16 x n32, 4 d-tiles, k = 64 in 4 k16 steps)
        float oo[4][4];
        #pragma unroll
        for (int dt = 0; dt < 4; ++dt)
            oo[dt][0] = oo[dt][1] = oo[dt][2] = oo[dt][3] = 0.f;
        #pragma unroll
        for (int kk = 0; kk < 4; ++kk) {
            #pragma unroll
            for (int dt = 0; dt < 4; ++dt) {
                const __half* vrow = vT + (h * 32 + dt * 8 + gid) * VTS + kk * 16 + tg * 2;
                uint32_t vb[2] = { *(const uint32_t*)(vrow),
                                   *(const uint32_t*)(vrow + 8) };
                mma_f16(oo[dt], pa[kk], vb);
            }
        }

        // O -> aoF (fp16 A-frag image in sA region)
        #pragma unroll
        for (int dt = 0; dt < 4; ++dt) {
            int d0 = h * 32 + dt * 8 + tg * 2;
            stageAw(sA, r0 + gid,     d0, hpack(oo[dt][0], oo[dt][1]));
            stageAw(sA, r0 + gid + 8, d0, hpack(oo[dt][2], oo[dt][3]));
        }
    }
    __syncthreads();

    // ---- phase 4: projection GEMM + bias + un-window ----
    float* obase = out + (((size_t)(b * 256 + nh * 8) * 256 + nww * 8) << 8);
    for (int ch = 0; ch < 2; ++ch) {
        __syncthreads();
        const uint4* srcB = (const uint4*)&g_wH[96 + ch * 16][0][0][0];
        uint4* dB = (uint4*)sB;
        #pragma unroll
        for (int i = 0; i < 8; ++i) dB[t + i * 512] = srcB[t + i * 512];
        __syncthreads();
        float acc[2][2][4];
        gemm_m32n16(sA, sB, mw, nwp, lane, acc);
        #pragma unroll
        for (int m = 0; m < 2; ++m) {
            int row = (2 * mw + m) * 16 + gid;
            #pragma unroll
            for (int nt = 0; nt < 2; ++nt) {
                int c = ch * 128 + (nwp * 2 + nt) * 8 + tg * 2;
                float2 bias = *(const float2*)(bp + c);
                int r0 = row, r1 = row + 8;
                *(float2*)(obase + (r0 >> 3) * 65536 + (r0 & 7) * 256 + c) =
                    make_float2(acc[m][nt][0] + bias.x, acc[m][nt][1] + bias.y);
                *(float2*)(obase + (r1 >> 3) * 65536 + (r1 & 7) * 256 + c) =
                    make_float2(acc[m][nt][2] + bias.x, acc[m][nt][3] + bias.y);
            }
        }
    }
}

extern "C" void kernel_launch(void* const* d_in, const int* in_sizes, int n_in,
                              void* d_out, int out_size)
{
    const float* x   = (const float*)d_in[0];
    const float* Wq  = (const float*)d_in[1];
    const float* Wkv = (const float*)d_in[2];
    const float* pos = (const float*)d_in[3];
    const float* Wp  = (const float*)d_in[4];
    const float* bp  = (const float*)d_in[5];
    float* out = (float*)d_out;

    cudaFuncSetAttribute(k_fused, cudaFuncAttributeMaxDynamicSharedMemorySize, SMEM_F);

    k0_prep<<<256, 512>>>(Wq, Wkv, Wp);
    k_fused<<<4096, 512, SMEM_F>>>(x, pos, bp, out);
}